// round 16
// baseline (speedup 1.0000x reference)
#include <cuda_runtime.h>
#include <cuda_bf16.h>
#include <cstdint>

#define BATCH 2
#define SEQ 2048
#define DMODEL 2048
#define NHEADS 16
#define HDIM 128
#define HHDIM 64

typedef unsigned long long ull;

// ---------------- scratch (device globals: no allocations allowed) -----------
__device__ float g_xq[BATCH * SEQ * NHEADS * HDIM];
__device__ float g_xk[BATCH * SEQ * NHEADS * HDIM];
__device__ float g_xv[BATCH * SEQ * NHEADS * HDIM];
__device__ float g_lambda;

// int8 GEMM operands: q = 128*hi + lo  (hi in ±127, lo in ±64)
__device__ char g_xs8h[BATCH * SEQ * DMODEL];
__device__ char g_xs8l[BATCH * SEQ * DMODEL];
__device__ char g_as8h[BATCH * SEQ * DMODEL];
__device__ char g_as8l[BATCH * SEQ * DMODEL];
__device__ char g_ws8h[4][DMODEL * DMODEL];   // q,k,v,o
__device__ char g_ws8l[4][DMODEL * DMODEL];

// flash operands (bf16 hi/lo, unscaled) — proven round-13 path
__device__ __nv_bfloat16 g_qhi[BATCH * SEQ * DMODEL];
__device__ __nv_bfloat16 g_qlo[BATCH * SEQ * DMODEL];
__device__ __nv_bfloat16 g_khi[BATCH * SEQ * DMODEL];
__device__ __nv_bfloat16 g_klo[BATCH * SEQ * DMODEL];
__device__ __nv_bfloat16 g_vhiT[BATCH * NHEADS * HDIM * SEQ];  // [bh][d][s]
__device__ __nv_bfloat16 g_vloT[BATCH * NHEADS * HDIM * SEQ];
__device__ float g_attn1[BATCH * NHEADS * SEQ * HDIM];         // [bh][s][d]
__device__ float g_attn2[BATCH * NHEADS * SEQ * HDIM];

// ---------------- helpers ----------------------------------------------------
__device__ __forceinline__ uint32_t smem_u32(const void* p) {
    uint32_t a;
    asm("{ .reg .u64 t; cvta.to.shared.u64 t, %1; cvt.u32.u64 %0, t; }" : "=r"(a) : "l"(p));
    return a;
}
__device__ __forceinline__ void ldsm4(uint32_t* r, uint32_t addr) {
    asm volatile("ldmatrix.sync.aligned.m8n8.x4.shared.b16 {%0,%1,%2,%3}, [%4];"
                 : "=r"(r[0]), "=r"(r[1]), "=r"(r[2]), "=r"(r[3]) : "r"(addr));
}
// fp32-accum bf16 mma (flash path)
__device__ __forceinline__ void mma16816(float* c, const uint32_t* a,
                                         uint32_t b0, uint32_t b1) {
    asm volatile("mma.sync.aligned.m16n8k16.row.col.f32.bf16.bf16.f32 "
                 "{%0,%1,%2,%3}, {%4,%5,%6,%7}, {%8,%9}, {%0,%1,%2,%3};"
                 : "+f"(c[0]), "+f"(c[1]), "+f"(c[2]), "+f"(c[3])
                 : "r"(a[0]), "r"(a[1]), "r"(a[2]), "r"(a[3]), "r"(b0), "r"(b1));
}
// s32-accum int8 mma, k=32
__device__ __forceinline__ void mma_s8(int* c, const uint32_t* a,
                                       uint32_t b0, uint32_t b1) {
    asm volatile("mma.sync.aligned.m16n8k32.row.col.s32.s8.s8.s32 "
                 "{%0,%1,%2,%3}, {%4,%5,%6,%7}, {%8,%9}, {%0,%1,%2,%3};"
                 : "+r"(c[0]), "+r"(c[1]), "+r"(c[2]), "+r"(c[3])
                 : "r"(a[0]), "r"(a[1]), "r"(a[2]), "r"(a[3]), "r"(b0), "r"(b1));
}
__device__ __forceinline__ void cp16(uint32_t saddr, const void* g) {
    asm volatile("cp.async.cg.shared.global [%0], [%1], 16;" :: "r"(saddr), "l"(g));
}
__device__ __forceinline__ void cp_commit() { asm volatile("cp.async.commit_group;"); }
__device__ __forceinline__ void cp_wait1()  { asm volatile("cp.async.wait_group 1;" ::: "memory"); }
__device__ __forceinline__ void cp_wait0()  { asm volatile("cp.async.wait_group 0;" ::: "memory"); }
// bf16 packing (flash path)
__device__ __forceinline__ uint32_t packbf(float lo, float hi) {
    uint32_t r; asm("cvt.rn.bf16x2.f32 %0, %1, %2;" : "=r"(r) : "f"(hi), "f"(lo)); return r;
}
__device__ __forceinline__ float bflo(uint32_t v) { return __uint_as_float(v << 16); }
__device__ __forceinline__ float bfhi(uint32_t v) { return __uint_as_float(v & 0xffff0000u); }

// ---------------- int8 15-bit quantize: q = 128*h + l ------------------------
__device__ __forceinline__ void quant1(float a, float S, int& h, int& l) {
    float q = rintf(fminf(fmaxf(a * S, -16256.f), 16256.f));
    float hf = rintf(q * 0.0078125f);
    h = (int)hf;
    l = (int)(q - 128.f * hf);
}

__global__ void quant_s8(const float* __restrict__ src, char* __restrict__ hi,
                         char* __restrict__ lo, int n, float S) {
    int i = (blockIdx.x * blockDim.x + threadIdx.x) * 4;
    if (i >= n) return;
    float4 v = *(const float4*)(src + i);
    int h0, l0, h1, l1, h2, l2, h3, l3;
    quant1(v.x, S, h0, l0); quant1(v.y, S, h1, l1);
    quant1(v.z, S, h2, l2); quant1(v.w, S, h3, l3);
    uint32_t hp = (h0 & 255) | ((h1 & 255) << 8) | ((h2 & 255) << 16) | ((uint32_t)(h3 & 255) << 24);
    uint32_t lp = (l0 & 255) | ((l1 & 255) << 8) | ((l2 & 255) << 16) | ((uint32_t)(l3 & 255) << 24);
    *(uint32_t*)(hi + i) = hp;
    *(uint32_t*)(lo + i) = lp;
}

// ---------------- int8 split HMMA GEMM (k32, 3 exact products) ---------------
// Y[4096,2048] = A @ W^T.  512 thr, CTA 128x128, 16 warps (4m x 4n), warp 32x32.
// K chunk = 64 int8 bytes per row, 2-stage cp.async.
#define TSTR 80
#define SBUF (128 * TSTR)            // 10240
#define S_ALO SBUF
#define S_BHI (2 * SBUF)
#define S_BLO (3 * SBUF)
#define SSTG (4 * SBUF)              // 40960
#define GEMM_SMEM (2 * SSTG)         // 81920
#define NCHS8 (DMODEL / 64)          // 32

struct GemmB { const char* bh; const char* bl; float* y; };

__global__ __launch_bounds__(512, 1)
void gemm_s8(const char* __restrict__ Ahp, const char* __restrict__ Alp,
             GemmB b0, GemmB b1, GemmB b2, float s2, float s1) {
    extern __shared__ char smem[];
    const uint32_t sb = smem_u32(smem);
    const int tid = threadIdx.x, wid = tid >> 5, lane = tid & 31;
    const int n0 = blockIdx.x * 128, m0 = blockIdx.y * 128;
    GemmB g = (blockIdx.z == 0) ? b0 : ((blockIdx.z == 1) ? b1 : b2);

    const char* Ah = Ahp + (size_t)m0 * DMODEL;
    const char* Al = Alp + (size_t)m0 * DMODEL;
    const char* Bh = g.bh + (size_t)n0 * DMODEL;
    const char* Bl = g.bl + (size_t)n0 * DMODEL;

    const int row = tid >> 2, ch = tid & 3;     // 128 rows x 4 16B chunks = 512

    int c2[2][4][4], c1[2][4][4];
#pragma unroll
    for (int mt = 0; mt < 2; mt++)
#pragma unroll
        for (int nb = 0; nb < 4; nb++)
#pragma unroll
            for (int j = 0; j < 4; j++) { c2[mt][nb][j] = 0; c1[mt][nb][j] = 0; }

    // prologue: chunk 0 -> stage 0
    {
        size_t go = (size_t)row * DMODEL + ch * 16;
        uint32_t so = row * TSTR + ch * 16;
        cp16(sb + so, Ah + go);
        cp16(sb + S_ALO + so, Al + go);
        cp16(sb + S_BHI + so, Bh + go);
        cp16(sb + S_BLO + so, Bl + go);
        cp_commit();
    }

    const int wm = wid >> 2, wn = wid & 3;
    const int lrow = (lane & 7) + ((lane >> 3) & 1) * 8;
    const int l16 = lane >> 4;

    for (int c = 0; c < NCHS8; c++) {
        if (c + 1 < NCHS8) {
            uint32_t stb = sb + ((c + 1) & 1) * SSTG;
            size_t go = (size_t)row * DMODEL + (c + 1) * 64 + ch * 16;
            uint32_t so = row * TSTR + ch * 16;
            cp16(stb + so, Ah + go);
            cp16(stb + S_ALO + so, Al + go);
            cp16(stb + S_BHI + so, Bh + go);
            cp16(stb + S_BLO + so, Bl + go);
            cp_commit();
            cp_wait1();
        } else {
            cp_wait0();
        }
        __syncthreads();

        const uint32_t stb = sb + (c & 1) * SSTG;
#pragma unroll
        for (int s = 0; s < 2; s++) {             // two k32 steps per 64B chunk
            uint32_t bh4[2][4], bl4[2][4];
#pragma unroll
            for (int p = 0; p < 2; p++) {
                uint32_t off = (wn * 32 + p * 16 + lrow) * TSTR + s * 32 + l16 * 16;
                ldsm4(bh4[p], stb + S_BHI + off);
                ldsm4(bl4[p], stb + S_BLO + off);
            }
#pragma unroll
            for (int mt = 0; mt < 2; mt++) {
                uint32_t ah[4], al[4];
                uint32_t off = (wm * 32 + mt * 16 + lrow) * TSTR + s * 32 + l16 * 16;
                ldsm4(ah, stb + off);
                ldsm4(al, stb + S_ALO + off);
#pragma unroll
                for (int p = 0; p < 2; p++)
#pragma unroll
                    for (int od = 0; od < 2; od++) {
                        const int nb = p * 2 + od;
                        mma_s8(c2[mt][nb], ah, bh4[p][od], bh4[p][od + 2]);   // hi*hi
                        mma_s8(c1[mt][nb], ah, bl4[p][od], bl4[p][od + 2]);   // hi*lo
                        mma_s8(c1[mt][nb], al, bh4[p][od], bh4[p][od + 2]);   // lo*hi
                    }
            }
        }
        __syncthreads();
    }

    // epilogue: y = s2*c2 + s1*c1
    const int erow = lane >> 2, ecol = (lane & 3) * 2;
#pragma unroll
    for (int mt = 0; mt < 2; mt++)
#pragma unroll
        for (int nb = 0; nb < 4; nb++) {
            int rg = m0 + wm * 32 + mt * 16 + erow;
            int cg = n0 + wn * 32 + nb * 8 + ecol;
            *(float2*)(g.y + (size_t)rg * DMODEL + cg) =
                make_float2(s2 * (float)c2[mt][nb][0] + s1 * (float)c1[mt][nb][0],
                            s2 * (float)c2[mt][nb][1] + s1 * (float)c1[mt][nb][1]);
            *(float2*)(g.y + (size_t)(rg + 8) * DMODEL + cg) =
                make_float2(s2 * (float)c2[mt][nb][2] + s1 * (float)c1[mt][nb][2],
                            s2 * (float)c2[mt][nb][3] + s1 * (float)c1[mt][nb][3]);
        }
}

// ---------------- fused RoPE + scale + bf16 split (Q and K) ------------------
__global__ void rope_split_kernel(const float* __restrict__ fc) {
    int idx = blockIdx.x * blockDim.x + threadIdx.x;
    const int NP = BATCH * SEQ * NHEADS * HHDIM;
    if (idx >= NP) return;
    const float* buf;
    __nv_bfloat16 *dhi, *dlo;
    float scale;
    if (blockIdx.y == 0) { buf = g_xq; dhi = g_qhi; dlo = g_qlo; scale = 0.125f; }
    else                 { buf = g_xk; dhi = g_khi; dlo = g_klo; scale = 1.0f; }
    int d2 = idx & 63;
    int h  = (idx >> 6) & 15;
    int s  = (idx >> 10) & 2047;
    int b  = idx >> 21;
    size_t base = ((size_t)((b * SEQ + s) * NHEADS + h) << 7) + d2 * 2;
    const float* p = buf + base;
    const float* f = fc + s * 256 + d2 * 4;
    float e = p[0], o = p[1];
    float e2 = (e * f[0] + o * f[1]) * scale;
    float o2 = (e * f[2] + o * f[3]) * scale;
    uint32_t hp = packbf(e2, o2);
    uint32_t lp = packbf(e2 - bflo(hp), o2 - bfhi(hp));
    *(uint32_t*)(dhi + base) = hp;
    *(uint32_t*)(dlo + base) = lp;
}

// ---------------- V transpose + split:  [b][s][h][d] -> [bh][d][s] -----------
__global__ void vsplitT_kernel() {
    __shared__ float tile[32][33];
    int bh = blockIdx.z, b = bh >> 4, h = bh & 15;
    int stile = blockIdx.x, dt = blockIdx.y;
    int t = threadIdx.x, tr = t >> 5, tc = t & 31;
#pragma unroll
    for (int i = 0; i < 4; i++) {
        int sl = tr + i * 8;
        tile[sl][tc] = g_xv[(size_t)((b * SEQ + stile * 32 + sl) * NHEADS + h) * HDIM + dt * 32 + tc];
    }
    __syncthreads();
#pragma unroll
    for (int i = 0; i < 4; i++) {
        int dl = tr + i * 8;
        float v = tile[tc][dl];
        size_t dst = (size_t)bh * (HDIM * SEQ) + (size_t)(dt * 32 + dl) * SEQ + stile * 32 + tc;
        __nv_bfloat16 hv = __float2bfloat16(v);
        g_vhiT[dst] = hv;
        g_vloT[dst] = __float2bfloat16(v - __bfloat162float(hv));
    }
}

// ---------------- lambda scalar ---------------------------------------------
__global__ void lambda_kernel(const float* __restrict__ lq1, const float* __restrict__ lk1,
                              const float* __restrict__ lq2, const float* __restrict__ lk2) {
    int t = threadIdx.x;
    float s1 = lq1[t] * lk1[t] + lq1[t + 32] * lk1[t + 32];
    float s2 = lq2[t] * lk2[t] + lq2[t + 32] * lk2[t + 32];
#pragma unroll
    for (int o = 16; o; o >>= 1) {
        s1 += __shfl_xor_sync(0xffffffffu, s1, o);
        s2 += __shfl_xor_sync(0xffffffffu, s2, o);
    }
    if (t == 0) g_lambda = expf(s1) - expf(s2) + 0.2f;
}

// ---------------- HMMA differential flash attention (round-13, proven) -------
#define FTSTR 144
#define KT_B (64 * FTSTR)
#define VT_B (128 * FTSTR)
#define FSTG (2 * KT_B + 2 * VT_B)
#define FLASH_SMEM (2 * FSTG)

#define FLASH_LOAD_TILE(kt, s) do {                                              \
    uint32_t stg_ = sb + (s) * FSTG;                                             \
    for (int i_ = 0; i_ < 2; i_++) {                                             \
        int t_ = tid + i_ * 256; int row_ = t_ >> 3, ch_ = t_ & 7;               \
        size_t src_ = (size_t)((kt) * 64 + row_) * 2048 + ch_ * 8;               \
        cp16(stg_ + row_ * FTSTR + ch_ * 16, Kh + src_);                         \
        cp16(stg_ + KT_B + row_ * FTSTR + ch_ * 16, Kl + src_);                  \
    }                                                                            \
    for (int i_ = 0; i_ < 4; i_++) {                                             \
        int t_ = tid + i_ * 256; int row_ = t_ >> 3, ch_ = t_ & 7;               \
        size_t src_ = (size_t)row_ * 2048 + (kt) * 64 + ch_ * 8;                 \
        cp16(stg_ + 2 * KT_B + row_ * FTSTR + ch_ * 16, Vh + src_);              \
        cp16(stg_ + 2 * KT_B + VT_B + row_ * FTSTR + ch_ * 16, Vl + src_);       \
    }                                                                            \
    cp_commit();                                                                 \
} while (0)

__global__ __launch_bounds__(256, 1)
void flash_hmma() {
    extern __shared__ char fsm[];
    const uint32_t sb = smem_u32(fsm);
    const int tid = threadIdx.x, wid = tid >> 5, lane = tid & 31;
    const int qb = blockIdx.x, bh = blockIdx.y, st = blockIdx.z;
    const int b = bh >> 4, h = bh & 15;
    const int ntiles = 2 * qb + 2;

    const size_t qkbase = (size_t)b * (SEQ * DMODEL) + (size_t)h * HDIM + st * 64;
    const __nv_bfloat16* Qh = g_qhi + qkbase;
    const __nv_bfloat16* Ql = g_qlo + qkbase;
    const __nv_bfloat16* Kh = g_khi + qkbase;
    const __nv_bfloat16* Kl = g_klo + qkbase;
    const __nv_bfloat16* Vh = g_vhiT + (size_t)bh * (HDIM * SEQ);
    const __nv_bfloat16* Vl = g_vloT + (size_t)bh * (HDIM * SEQ);
    float* Og = (st == 0 ? g_attn1 : g_attn2) + (size_t)bh * (SEQ * HDIM);

#pragma unroll
    for (int i = 0; i < 4; i++) {
        int t = tid + i * 256;
        int row = t >> 3, ch = t & 7;
        size_t src = (size_t)(qb * 128 + row) * 2048 + ch * 8;
        cp16(sb + 2 * KT_B + row * FTSTR + ch * 16, Qh + src);
        cp16(sb + 2 * KT_B + VT_B + row * FTSTR + ch * 16, Ql + src);
    }
    cp_commit();
    cp_wait0();
    __syncthreads();

    const int lrow = (lane & 7) + ((lane >> 3) & 1) * 8;
    const int l16 = lane >> 4;

    uint32_t qh[4][4], ql[4][4];
#pragma unroll
    for (int ks = 0; ks < 4; ks++) {
        uint32_t off = (wid * 16 + lrow) * FTSTR + (ks * 2 + l16) * 16;
        ldsm4(qh[ks], sb + 2 * KT_B + off);
        ldsm4(ql[ks], sb + 2 * KT_B + VT_B + off);
    }
    __syncthreads();

    FLASH_LOAD_TILE(0, 0);

    float m0 = -1e30f, m1 = -1e30f, l0 = 0.f, l1 = 0.f;
    float oacc[16][4];
#pragma unroll
    for (int t = 0; t < 16; t++)
#pragma unroll
        for (int j = 0; j < 4; j++) oacc[t][j] = 0.f;

    const int r0g = qb * 128 + wid * 16 + (lane >> 2);
    const int colb = 2 * (lane & 3);

    for (int kt = 0; kt < ntiles; kt++) {
        if (kt + 1 < ntiles) { FLASH_LOAD_TILE(kt + 1, (kt + 1) & 1); cp_wait1(); }
        else cp_wait0();
        __syncthreads();
        const uint32_t stg = sb + (kt & 1) * FSTG;

        float sacc[8][4];
#pragma unroll
        for (int j = 0; j < 8; j++)
#pragma unroll
            for (int k = 0; k < 4; k++) sacc[j][k] = 0.f;
#pragma unroll
        for (int ks = 0; ks < 4; ks++) {
            uint32_t kh[4][4], kl[4][4];
#pragma unroll
            for (int p = 0; p < 4; p++) {
                uint32_t off = (p * 16 + lrow) * FTSTR + (ks * 2 + l16) * 16;
                ldsm4(kh[p], stg + off);
                ldsm4(kl[p], stg + KT_B + off);
            }
#pragma unroll
            for (int p = 0; p < 4; p++)
#pragma unroll
                for (int od = 0; od < 2; od++) {
                    float* s = sacc[p * 2 + od];
                    mma16816(s, qh[ks], kh[p][od], kh[p][od + 2]);
                    mma16816(s, qh[ks], kl[p][od], kl[p][od + 2]);
                    mma16816(s, ql[ks], kh[p][od], kh[p][od + 2]);
                }
        }

        if (kt >= 2 * qb) {
            int cb = kt * 64 + colb;
#pragma unroll
            for (int j = 0; j < 8; j++) {
                int c0 = cb + j * 8;
                if (c0 > r0g)     sacc[j][0] = -1e30f;
                if (c0 + 1 > r0g) sacc[j][1] = -1e30f;
                if (c0 > r0g + 8)     sacc[j][2] = -1e30f;
                if (c0 + 1 > r0g + 8) sacc[j][3] = -1e30f;
            }
        }

        float mx0 = -1e30f, mx1 = -1e30f;
#pragma unroll
        for (int j = 0; j < 8; j++) {
            mx0 = fmaxf(mx0, fmaxf(sacc[j][0], sacc[j][1]));
            mx1 = fmaxf(mx1, fmaxf(sacc[j][2], sacc[j][3]));
        }
        mx0 = fmaxf(mx0, __shfl_xor_sync(0xffffffffu, mx0, 1));
        mx0 = fmaxf(mx0, __shfl_xor_sync(0xffffffffu, mx0, 2));
        mx1 = fmaxf(mx1, __shfl_xor_sync(0xffffffffu, mx1, 1));
        mx1 = fmaxf(mx1, __shfl_xor_sync(0xffffffffu, mx1, 2));
        float mn0 = fmaxf(m0, mx0), mn1 = fmaxf(m1, mx1);
        float cr0 = __expf(m0 - mn0), cr1 = __expf(m1 - mn1);
        float ps0 = 0.f, ps1 = 0.f;
#pragma unroll
        for (int j = 0; j < 8; j++) {
            sacc[j][0] = __expf(sacc[j][0] - mn0); ps0 += sacc[j][0];
            sacc[j][1] = __expf(sacc[j][1] - mn0); ps0 += sacc[j][1];
            sacc[j][2] = __expf(sacc[j][2] - mn1); ps1 += sacc[j][2];
            sacc[j][3] = __expf(sacc[j][3] - mn1); ps1 += sacc[j][3];
        }
        ps0 += __shfl_xor_sync(0xffffffffu, ps0, 1);
        ps0 += __shfl_xor_sync(0xffffffffu, ps0, 2);
        ps1 += __shfl_xor_sync(0xffffffffu, ps1, 1);
        ps1 += __shfl_xor_sync(0xffffffffu, ps1, 2);
        l0 = l0 * cr0 + ps0; l1 = l1 * cr1 + ps1;
        m0 = mn0; m1 = mn1;
#pragma unroll
        for (int t = 0; t < 16; t++) {
            oacc[t][0] *= cr0; oacc[t][1] *= cr0;
            oacc[t][2] *= cr1; oacc[t][3] *= cr1;
        }

        uint32_t phf[4][4], plf[4][4];
#pragma unroll
        for (int j2 = 0; j2 < 4; j2++) {
            float* ta = sacc[2 * j2];
            float* tb = sacc[2 * j2 + 1];
            phf[j2][0] = packbf(ta[0], ta[1]);
            phf[j2][1] = packbf(ta[2], ta[3]);
            phf[j2][2] = packbf(tb[0], tb[1]);
            phf[j2][3] = packbf(tb[2], tb[3]);
            plf[j2][0] = packbf(ta[0] - bflo(phf[j2][0]), ta[1] - bfhi(phf[j2][0]));
            plf[j2][1] = packbf(ta[2] - bflo(phf[j2][1]), ta[3] - bfhi(phf[j2][1]));
            plf[j2][2] = packbf(tb[0] - bflo(phf[j2][2]), tb[1] - bfhi(phf[j2][2]));
            plf[j2][3] = packbf(tb[2] - bflo(phf[j2][3]), tb[3] - bfhi(phf[j2][3]));
        }

#pragma unroll
        for (int ks = 0; ks < 4; ks++) {
            uint32_t vf[8][4];
#pragma unroll
            for (int p = 0; p < 8; p++)
                ldsm4(vf[p], stg + 2 * KT_B + (p * 16 + lrow) * FTSTR + (ks * 2 + l16) * 16);
#pragma unroll
            for (int p = 0; p < 8; p++)
#pragma unroll
                for (int od = 0; od < 2; od++) {
                    mma16816(oacc[p * 2 + od], phf[ks], vf[p][od], vf[p][od + 2]);
                    mma16816(oacc[p * 2 + od], plf[ks], vf[p][od], vf[p][od + 2]);
                }
#pragma unroll
            for (int p = 0; p < 8; p++)
                ldsm4(vf[p], stg + 2 * KT_B + VT_B + (p * 16 + lrow) * FTSTR + (ks * 2 + l16) * 16);
#pragma unroll
            for (int p = 0; p < 8; p++)
#pragma unroll
                for (int od = 0; od < 2; od++)
                    mma16816(oacc[p * 2 + od], phf[ks], vf[p][od], vf[p][od + 2]);
        }
        __syncthreads();
    }

    float i0 = 1.f / l0, i1 = 1.f / l1;
    float* orow0 = Og + (size_t)(qb * 128 + wid * 16 + (lane >> 2)) * HDIM;
    float* orow1 = orow0 + 8 * HDIM;
#pragma unroll
    for (int t = 0; t < 16; t++) {
        int col = t * 8 + colb;
        *(float2*)(orow0 + col) = make_float2(oacc[t][0] * i0, oacc[t][1] * i0);
        *(float2*)(orow1 + col) = make_float2(oacc[t][2] * i1, oacc[t][3] * i1);
    }
}

// ---------------- combine: diff + RMSNorm + subln + 0.8 + int8 quant ---------
#define SATTN 3386.6667f   // 16256 / 4.8  (attn RMS = 0.8, clamp 6 sigma)

__global__ void combine_kernel(const float* __restrict__ subln) {
    int row = blockIdx.x * 8 + (threadIdx.x >> 5);
    int lane = threadIdx.x & 31;
    size_t off = (size_t)row * HDIM + lane * 4;
    float lam = g_lambda;
    float4 x1 = *(const float4*)(g_attn1 + off);
    float4 x2 = *(const float4*)(g_attn2 + off);
    float v0 = x1.x - lam * x2.x;
    float v1 = x1.y - lam * x2.y;
    float v2 = x1.z - lam * x2.z;
    float v3 = x1.w - lam * x2.w;
    float ss = v0 * v0 + v1 * v1 + v2 * v2 + v3 * v3;
#pragma unroll
    for (int o = 16; o; o >>= 1) ss += __shfl_xor_sync(0xffffffffu, ss, o);
    float rms = rsqrtf(ss * (1.0f / 128.0f) + 1e-5f);
    const float4 sw = *(const float4*)(subln + lane * 4);
    v0 *= rms * sw.x * 0.8f;
    v1 *= rms * sw.y * 0.8f;
    v2 *= rms * sw.z * 0.8f;
    v3 *= rms * sw.w * 0.8f;
    int h0, l0, h1, l1, h2, l2, h3, l3;
    quant1(v0, SATTN, h0, l0); quant1(v1, SATTN, h1, l1);
    quant1(v2, SATTN, h2, l2); quant1(v3, SATTN, h3, l3);
    uint32_t hp = (h0 & 255) | ((h1 & 255) << 8) | ((h2 & 255) << 16) | ((uint32_t)(h3 & 255) << 24);
    uint32_t lp = (l0 & 255) | ((l1 & 255) << 8) | ((l2 & 255) << 16) | ((uint32_t)(l3 & 255) << 24);
    *(uint32_t*)(g_as8h + off) = hp;
    *(uint32_t*)(g_as8l + off) = lp;
}

// ---------------- launch -----------------------------------------------------
extern "C" void kernel_launch(void* const* d_in, const int* in_sizes, int n_in,
                              void* d_out, int out_size) {
    const float* x    = (const float*)d_in[0];
    const float* fc   = (const float*)d_in[1];
    const float* w_in[4] = {(const float*)d_in[2], (const float*)d_in[3],
                            (const float*)d_in[4], (const float*)d_in[5]};
    const float* lq1  = (const float*)d_in[6];
    const float* lk1  = (const float*)d_in[7];
    const float* lq2  = (const float*)d_in[8];
    const float* lk2  = (const float*)d_in[9];
    const float* subw = (const float*)d_in[10];
    float* out = (float*)d_out;

    float *xq_p, *xk_p, *xv_p;
    char *xh, *xl, *ah, *al, *wh, *wl;
    cudaGetSymbolAddress((void**)&xq_p, g_xq);
    cudaGetSymbolAddress((void**)&xk_p, g_xk);
    cudaGetSymbolAddress((void**)&xv_p, g_xv);
    cudaGetSymbolAddress((void**)&xh, g_xs8h);
    cudaGetSymbolAddress((void**)&xl, g_xs8l);
    cudaGetSymbolAddress((void**)&ah, g_as8h);
    cudaGetSymbolAddress((void**)&al, g_as8l);
    cudaGetSymbolAddress((void**)&wh, g_ws8h);
    cudaGetSymbolAddress((void**)&wl, g_ws8l);

    const int NX = BATCH * SEQ * DMODEL;          // 8388608
    const int NW = DMODEL * DMODEL;               // 4194304
    const int NP = BATCH * SEQ * NHEADS * HHDIM;  // 4194304

    // scales: clamp everything at 6 sigma
    const double Sx = 16256.0 / 6.0;                        // x ~ N(0,1)
    const double Sw = 16256.0 / (6.0 / 45.254833995939045); // w ~ N(0, 1/2048)
    const double Sat = 16256.0 / 4.8;                       // attn RMS 0.8
    const float s2_qkv = (float)(16384.0 / (Sx * Sw));
    const float s1_qkv = (float)(128.0 / (Sx * Sw));
    const float s2_o   = (float)(16384.0 / (Sat * Sw));
    const float s1_o   = (float)(128.0 / (Sat * Sw));

    quant_s8<<<NX / 1024, 256>>>(x, xh, xl, NX, (float)Sx);
    for (int w = 0; w < 4; w++)
        quant_s8<<<NW / 1024, 256>>>(w_in[w], wh + (size_t)w * NW, wl + (size_t)w * NW,
                                     NW, (float)Sw);

    cudaFuncSetAttribute(gemm_s8, cudaFuncAttributeMaxDynamicSharedMemorySize, GEMM_SMEM);
    {
        GemmB bq = {wh + 0 * (size_t)NW, wl + 0 * (size_t)NW, xq_p};
        GemmB bk = {wh + 1 * (size_t)NW, wl + 1 * (size_t)NW, xk_p};
        GemmB bv = {wh + 2 * (size_t)NW, wl + 2 * (size_t)NW, xv_p};
        gemm_s8<<<dim3(DMODEL / 128, (BATCH * SEQ) / 128, 3), 512, GEMM_SMEM>>>(
            xh, xl, bq, bk, bv, s2_qkv, s1_qkv);
    }

    rope_split_kernel<<<dim3(NP / 256, 2), 256>>>(fc);
    vsplitT_kernel<<<dim3(SEQ / 32, HDIM / 32, BATCH * NHEADS), 256>>>();
    lambda_kernel<<<1, 32>>>(lq1, lk1, lq2, lk2);

    cudaFuncSetAttribute(flash_hmma, cudaFuncAttributeMaxDynamicSharedMemorySize, FLASH_SMEM);
    flash_hmma<<<dim3(SEQ / 128, BATCH * NHEADS, 2), 256, FLASH_SMEM>>>();

    combine_kernel<<<(BATCH * NHEADS * SEQ) / 8, 256>>>(subw);

    {
        GemmB bo = {wh + 3 * (size_t)NW, wl + 3 * (size_t)NW, out};
        gemm_s8<<<dim3(DMODEL / 128, (BATCH * SEQ) / 128, 1), 512, GEMM_SMEM>>>(
            ah, al, bo, bo, bo, s2_o, s1_o);
    }
}

// round 17
// speedup vs baseline: 1.7807x; 1.7807x over previous
#include <cuda_runtime.h>
#include <cuda_bf16.h>
#include <cstdint>

#define BATCH 2
#define SEQ 2048
#define DMODEL 2048
#define NHEADS 16
#define HDIM 128
#define HHDIM 64

typedef unsigned long long ull;

// ---------------- scratch (device globals: no allocations allowed) -----------
__device__ float g_xq[BATCH * SEQ * NHEADS * HDIM];
__device__ float g_xk[BATCH * SEQ * NHEADS * HDIM];
__device__ float g_xv[BATCH * SEQ * NHEADS * HDIM];
__device__ float g_lambda;

__device__ __nv_bfloat16 g_xhi[BATCH * SEQ * DMODEL];
__device__ __nv_bfloat16 g_xlo[BATCH * SEQ * DMODEL];
__device__ __nv_bfloat16 g_ahi[BATCH * SEQ * DMODEL];
__device__ __nv_bfloat16 g_alo[BATCH * SEQ * DMODEL];
__device__ __nv_bfloat16 g_whi[4][DMODEL * DMODEL];   // q,k,v,o
__device__ __nv_bfloat16 g_wlo[4][DMODEL * DMODEL];

// flash operands (bf16 hi/lo)
__device__ __nv_bfloat16 g_qhi[BATCH * SEQ * DMODEL];
__device__ __nv_bfloat16 g_qlo[BATCH * SEQ * DMODEL];
__device__ __nv_bfloat16 g_khi[BATCH * SEQ * DMODEL];
__device__ __nv_bfloat16 g_klo[BATCH * SEQ * DMODEL];
__device__ __nv_bfloat16 g_vhiT[BATCH * NHEADS * HDIM * SEQ];  // [bh][d][s]
__device__ __nv_bfloat16 g_vloT[BATCH * NHEADS * HDIM * SEQ];
__device__ float g_attn1[BATCH * NHEADS * SEQ * HDIM];         // [bh][s][d]
__device__ float g_attn2[BATCH * NHEADS * SEQ * HDIM];

// ---------------- helpers ----------------------------------------------------
__device__ __forceinline__ uint32_t smem_u32(const void* p) {
    uint32_t a;
    asm("{ .reg .u64 t; cvta.to.shared.u64 t, %1; cvt.u32.u64 %0, t; }" : "=r"(a) : "l"(p));
    return a;
}
__device__ __forceinline__ void ldsm4(uint32_t* r, uint32_t addr) {
    asm volatile("ldmatrix.sync.aligned.m8n8.x4.shared.b16 {%0,%1,%2,%3}, [%4];"
                 : "=r"(r[0]), "=r"(r[1]), "=r"(r[2]), "=r"(r[3]) : "r"(addr));
}
__device__ __forceinline__ void mma16816(float* c, const uint32_t* a,
                                         uint32_t b0, uint32_t b1) {
    asm volatile("mma.sync.aligned.m16n8k16.row.col.f32.bf16.bf16.f32 "
                 "{%0,%1,%2,%3}, {%4,%5,%6,%7}, {%8,%9}, {%0,%1,%2,%3};"
                 : "+f"(c[0]), "+f"(c[1]), "+f"(c[2]), "+f"(c[3])
                 : "r"(a[0]), "r"(a[1]), "r"(a[2]), "r"(a[3]), "r"(b0), "r"(b1));
}
__device__ __forceinline__ void cp16(uint32_t saddr, const void* g) {
    asm volatile("cp.async.cg.shared.global [%0], [%1], 16;" :: "r"(saddr), "l"(g));
}
__device__ __forceinline__ void cp_commit() { asm volatile("cp.async.commit_group;"); }
__device__ __forceinline__ void cp_wait1()  { asm volatile("cp.async.wait_group 1;" ::: "memory"); }
__device__ __forceinline__ void cp_wait0()  { asm volatile("cp.async.wait_group 0;" ::: "memory"); }
__device__ __forceinline__ uint32_t packbf(float lo, float hi) {
    uint32_t r; asm("cvt.rn.bf16x2.f32 %0, %1, %2;" : "=r"(r) : "f"(hi), "f"(lo)); return r;
}
__device__ __forceinline__ float bflo(uint32_t v) { return __uint_as_float(v << 16); }
__device__ __forceinline__ float bfhi(uint32_t v) { return __uint_as_float(v & 0xffff0000u); }

// ---------------- bf16 hi/lo split -------------------------------------------
__global__ void split_bf16(const float* __restrict__ src, __nv_bfloat16* __restrict__ hi,
                           __nv_bfloat16* __restrict__ lo, int n) {
    int i = (blockIdx.x * blockDim.x + threadIdx.x) * 4;
    if (i >= n) return;
    float4 v = *(const float4*)(src + i);
    uint32_t h01 = packbf(v.x, v.y), h23 = packbf(v.z, v.w);
    uint32_t l01 = packbf(v.x - bflo(h01), v.y - bfhi(h01));
    uint32_t l23 = packbf(v.z - bflo(h23), v.w - bfhi(h23));
    *(uint2*)(hi + i) = make_uint2(h01, h23);
    *(uint2*)(lo + i) = make_uint2(l01, l23);
}

// 4 weight tensors in one launch (grid.y selects the weight)
struct WSplit4 { const float* w[4]; };
__global__ void split_bf16_w4(WSplit4 ws, __nv_bfloat16* __restrict__ hi,
                              __nv_bfloat16* __restrict__ lo) {
    const int NW = DMODEL * DMODEL;
    size_t base = (size_t)blockIdx.y * NW;
    int i = (blockIdx.x * blockDim.x + threadIdx.x) * 4;
    float4 v = *(const float4*)(ws.w[blockIdx.y] + i);
    uint32_t h01 = packbf(v.x, v.y), h23 = packbf(v.z, v.w);
    uint32_t l01 = packbf(v.x - bflo(h01), v.y - bfhi(h01));
    uint32_t l23 = packbf(v.z - bflo(h23), v.w - bfhi(h23));
    *(uint2*)(hi + base + i) = make_uint2(h01, h23);
    *(uint2*)(lo + base + i) = make_uint2(l01, l23);
}

// ---------------- split-bf16 HMMA GEMM, 256x128 CTA tile ---------------------
// Y[4096, 2048] = A[4096, 2048] @ W[2048, 2048]^T via (hi+lo) bf16, 3 products.
// 512 thr = 16 warps (4M x 4N), warp tile 64x32 (identical to proven r13 warp).
// K chunk = 32. 2-stage cp.async.
#define TSTR 80
#define ABUF (256 * TSTR)            // 20480
#define BBUF (128 * TSTR)            // 10240
#define O_ALO ABUF
#define O_BHI (2 * ABUF)
#define O_BLO (2 * ABUF + BBUF)
#define STG_BYTES (2 * ABUF + 2 * BBUF)   // 61440
#define GEMM_SMEM (2 * STG_BYTES)         // 122880
#define NCH (DMODEL / 32)            // 64 k-chunks

struct GemmB { const __nv_bfloat16* bhi; const __nv_bfloat16* blo; float* y; };

__global__ __launch_bounds__(512, 1)
void gemm_mma(const __nv_bfloat16* __restrict__ Ahi, const __nv_bfloat16* __restrict__ Alo,
              GemmB b0, GemmB b1, GemmB b2) {
    extern __shared__ char smem[];
    const uint32_t sb = smem_u32(smem);
    const int tid = threadIdx.x, wid = tid >> 5, lane = tid & 31;
    const int n0 = blockIdx.x * 128, m0 = blockIdx.y * 256;
    GemmB g = (blockIdx.z == 0) ? b0 : ((blockIdx.z == 1) ? b1 : b2);

    const __nv_bfloat16* Ah = Ahi + (size_t)m0 * DMODEL;
    const __nv_bfloat16* Al = Alo + (size_t)m0 * DMODEL;
    const __nv_bfloat16* Bh = g.bhi + (size_t)n0 * DMODEL;
    const __nv_bfloat16* Bl = g.blo + (size_t)n0 * DMODEL;

    // loaders: A rows 256 x 4 chunks = 1024 cp per buf -> 2/thread; B 512 -> 1/thread
    const int arow = tid >> 2, ach = tid & 3;     // + 128 rows for i=1
    const int brow = tid >> 2, bch = tid & 3;

    float acc[4][4][4];
#pragma unroll
    for (int mt = 0; mt < 4; mt++)
#pragma unroll
        for (int nt = 0; nt < 4; nt++)
#pragma unroll
            for (int j = 0; j < 4; j++) acc[mt][nt][j] = 0.f;

    // prologue: chunk 0 -> stage 0
    {
#pragma unroll
        for (int i = 0; i < 2; i++) {
            int row = arow + i * 128;
            cp16(sb + row * TSTR + ach * 16, Ah + (size_t)row * DMODEL + ach * 8);
            cp16(sb + O_ALO + row * TSTR + ach * 16, Al + (size_t)row * DMODEL + ach * 8);
        }
        cp16(sb + O_BHI + brow * TSTR + bch * 16, Bh + (size_t)brow * DMODEL + bch * 8);
        cp16(sb + O_BLO + brow * TSTR + bch * 16, Bl + (size_t)brow * DMODEL + bch * 8);
        cp_commit();
    }

    const int wm = wid >> 2, wn = wid & 3;
    const int lrow = (lane & 7) + ((lane >> 3) & 1) * 8;
    const int l16 = lane >> 4;
    const int arow_base = wm * 64 + lrow;
    const int brow_base = wn * 32 + lrow;

    for (int c = 0; c < NCH; c++) {
        if (c + 1 < NCH) {
            uint32_t stb = sb + ((c + 1) & 1) * STG_BYTES;
            int k0 = (c + 1) * 32;
#pragma unroll
            for (int i = 0; i < 2; i++) {
                int row = arow + i * 128;
                cp16(stb + row * TSTR + ach * 16, Ah + (size_t)row * DMODEL + k0 + ach * 8);
                cp16(stb + O_ALO + row * TSTR + ach * 16, Al + (size_t)row * DMODEL + k0 + ach * 8);
            }
            cp16(stb + O_BHI + brow * TSTR + bch * 16, Bh + (size_t)brow * DMODEL + k0 + bch * 8);
            cp16(stb + O_BLO + brow * TSTR + bch * 16, Bl + (size_t)brow * DMODEL + k0 + bch * 8);
            cp_commit();
            cp_wait1();
        } else {
            cp_wait0();
        }
        __syncthreads();

        const uint32_t stb = sb + (c & 1) * STG_BYTES;
#pragma unroll
        for (int ks = 0; ks < 2; ks++) {
            const int ch = ks * 2 + l16;
            uint32_t bhi[2][4], blo[2][4];
#pragma unroll
            for (int p = 0; p < 2; p++) {
                uint32_t off = (brow_base + p * 16) * TSTR + ch * 16;
                ldsm4(bhi[p], stb + O_BHI + off);
                ldsm4(blo[p], stb + O_BLO + off);
            }
#pragma unroll
            for (int mt = 0; mt < 4; mt++) {
                uint32_t ahf[4], alf[4];
                uint32_t off = (arow_base + mt * 16) * TSTR + ch * 16;
                ldsm4(ahf, stb + off);
                ldsm4(alf, stb + O_ALO + off);
#pragma unroll
                for (int nt = 0; nt < 4; nt++) {
                    const int p = nt >> 1, od = nt & 1;
                    mma16816(acc[mt][nt], ahf, bhi[p][od], bhi[p][od + 2]);
                    mma16816(acc[mt][nt], ahf, blo[p][od], blo[p][od + 2]);
                    mma16816(acc[mt][nt], alf, bhi[p][od], bhi[p][od + 2]);
                }
            }
        }
        __syncthreads();
    }

    const int erow = lane >> 2, ecol = (lane & 3) * 2;
#pragma unroll
    for (int mt = 0; mt < 4; mt++)
#pragma unroll
        for (int nt = 0; nt < 4; nt++) {
            int rg = m0 + wm * 64 + mt * 16 + erow;
            int cg = n0 + wn * 32 + nt * 8 + ecol;
            *(float2*)(g.y + (size_t)rg * DMODEL + cg) =
                make_float2(acc[mt][nt][0], acc[mt][nt][1]);
            *(float2*)(g.y + (size_t)(rg + 8) * DMODEL + cg) =
                make_float2(acc[mt][nt][2], acc[mt][nt][3]);
        }
}

// ---------------- fused RoPE + scale + bf16 split (Q and K) ------------------
__global__ void rope_split_kernel(const float* __restrict__ fc) {
    int idx = blockIdx.x * blockDim.x + threadIdx.x;
    const int NP = BATCH * SEQ * NHEADS * HHDIM;
    if (idx >= NP) return;
    const float* buf;
    __nv_bfloat16 *dhi, *dlo;
    float scale;
    if (blockIdx.y == 0) { buf = g_xq; dhi = g_qhi; dlo = g_qlo; scale = 0.125f; }
    else                 { buf = g_xk; dhi = g_khi; dlo = g_klo; scale = 1.0f; }
    int d2 = idx & 63;
    int h  = (idx >> 6) & 15;
    int s  = (idx >> 10) & 2047;
    int b  = idx >> 21;
    size_t base = ((size_t)((b * SEQ + s) * NHEADS + h) << 7) + d2 * 2;
    const float* p = buf + base;
    const float* f = fc + s * 256 + d2 * 4;
    float e = p[0], o = p[1];
    float e2 = (e * f[0] + o * f[1]) * scale;
    float o2 = (e * f[2] + o * f[3]) * scale;
    uint32_t hp = packbf(e2, o2);
    uint32_t lp = packbf(e2 - bflo(hp), o2 - bfhi(hp));
    *(uint32_t*)(dhi + base) = hp;
    *(uint32_t*)(dlo + base) = lp;
}

// ---------------- V transpose + split:  [b][s][h][d] -> [bh][d][s] -----------
__global__ void vsplitT_kernel() {
    __shared__ float tile[32][33];
    int bh = blockIdx.z, b = bh >> 4, h = bh & 15;
    int stile = blockIdx.x, dt = blockIdx.y;
    int t = threadIdx.x, tr = t >> 5, tc = t & 31;
#pragma unroll
    for (int i = 0; i < 4; i++) {
        int sl = tr + i * 8;
        tile[sl][tc] = g_xv[(size_t)((b * SEQ + stile * 32 + sl) * NHEADS + h) * HDIM + dt * 32 + tc];
    }
    __syncthreads();
#pragma unroll
    for (int i = 0; i < 4; i++) {
        int dl = tr + i * 8;
        float v = tile[tc][dl];
        size_t dst = (size_t)bh * (HDIM * SEQ) + (size_t)(dt * 32 + dl) * SEQ + stile * 32 + tc;
        __nv_bfloat16 hv = __float2bfloat16(v);
        g_vhiT[dst] = hv;
        g_vloT[dst] = __float2bfloat16(v - __bfloat162float(hv));
    }
}

// ---------------- lambda scalar ---------------------------------------------
__global__ void lambda_kernel(const float* __restrict__ lq1, const float* __restrict__ lk1,
                              const float* __restrict__ lq2, const float* __restrict__ lk2) {
    int t = threadIdx.x;
    float s1 = lq1[t] * lk1[t] + lq1[t + 32] * lk1[t + 32];
    float s2 = lq2[t] * lk2[t] + lq2[t + 32] * lk2[t + 32];
#pragma unroll
    for (int o = 16; o; o >>= 1) {
        s1 += __shfl_xor_sync(0xffffffffu, s1, o);
        s2 += __shfl_xor_sync(0xffffffffu, s2, o);
    }
    if (t == 0) g_lambda = expf(s1) - expf(s2) + 0.2f;
}

// ---------------- HMMA differential flash attention (round-13, proven) -------
#define FTSTR 144
#define KT_B (64 * FTSTR)
#define VT_B (128 * FTSTR)
#define FSTG (2 * KT_B + 2 * VT_B)
#define FLASH_SMEM (2 * FSTG)

#define FLASH_LOAD_TILE(kt, s) do {                                              \
    uint32_t stg_ = sb + (s) * FSTG;                                             \
    for (int i_ = 0; i_ < 2; i_++) {                                             \
        int t_ = tid + i_ * 256; int row_ = t_ >> 3, ch_ = t_ & 7;               \
        size_t src_ = (size_t)((kt) * 64 + row_) * 2048 + ch_ * 8;               \
        cp16(stg_ + row_ * FTSTR + ch_ * 16, Kh + src_);                         \
        cp16(stg_ + KT_B + row_ * FTSTR + ch_ * 16, Kl + src_);                  \
    }                                                                            \
    for (int i_ = 0; i_ < 4; i_++) {                                             \
        int t_ = tid + i_ * 256; int row_ = t_ >> 3, ch_ = t_ & 7;               \
        size_t src_ = (size_t)row_ * 2048 + (kt) * 64 + ch_ * 8;                 \
        cp16(stg_ + 2 * KT_B + row_ * FTSTR + ch_ * 16, Vh + src_);              \
        cp16(stg_ + 2 * KT_B + VT_B + row_ * FTSTR + ch_ * 16, Vl + src_);       \
    }                                                                            \
    cp_commit();                                                                 \
} while (0)

__global__ __launch_bounds__(256, 1)
void flash_hmma() {
    extern __shared__ char fsm[];
    const uint32_t sb = smem_u32(fsm);
    const int tid = threadIdx.x, wid = tid >> 5, lane = tid & 31;
    const int qb = blockIdx.x, bh = blockIdx.y, st = blockIdx.z;
    const int b = bh >> 4, h = bh & 15;
    const int ntiles = 2 * qb + 2;

    const size_t qkbase = (size_t)b * (SEQ * DMODEL) + (size_t)h * HDIM + st * 64;
    const __nv_bfloat16* Qh = g_qhi + qkbase;
    const __nv_bfloat16* Ql = g_qlo + qkbase;
    const __nv_bfloat16* Kh = g_khi + qkbase;
    const __nv_bfloat16* Kl = g_klo + qkbase;
    const __nv_bfloat16* Vh = g_vhiT + (size_t)bh * (HDIM * SEQ);
    const __nv_bfloat16* Vl = g_vloT + (size_t)bh * (HDIM * SEQ);
    float* Og = (st == 0 ? g_attn1 : g_attn2) + (size_t)bh * (SEQ * HDIM);

#pragma unroll
    for (int i = 0; i < 4; i++) {
        int t = tid + i * 256;
        int row = t >> 3, ch = t & 7;
        size_t src = (size_t)(qb * 128 + row) * 2048 + ch * 8;
        cp16(sb + 2 * KT_B + row * FTSTR + ch * 16, Qh + src);
        cp16(sb + 2 * KT_B + VT_B + row * FTSTR + ch * 16, Ql + src);
    }
    cp_commit();
    cp_wait0();
    __syncthreads();

    const int lrow = (lane & 7) + ((lane >> 3) & 1) * 8;
    const int l16 = lane >> 4;

    uint32_t qh[4][4], ql[4][4];
#pragma unroll
    for (int ks = 0; ks < 4; ks++) {
        uint32_t off = (wid * 16 + lrow) * FTSTR + (ks * 2 + l16) * 16;
        ldsm4(qh[ks], sb + 2 * KT_B + off);
        ldsm4(ql[ks], sb + 2 * KT_B + VT_B + off);
    }
    __syncthreads();

    FLASH_LOAD_TILE(0, 0);

    float m0 = -1e30f, m1 = -1e30f, l0 = 0.f, l1 = 0.f;
    float oacc[16][4];
#pragma unroll
    for (int t = 0; t < 16; t++)
#pragma unroll
        for (int j = 0; j < 4; j++) oacc[t][j] = 0.f;

    const int r0g = qb * 128 + wid * 16 + (lane >> 2);
    const int colb = 2 * (lane & 3);

    for (int kt = 0; kt < ntiles; kt++) {
        if (kt + 1 < ntiles) { FLASH_LOAD_TILE(kt + 1, (kt + 1) & 1); cp_wait1(); }
        else cp_wait0();
        __syncthreads();
        const uint32_t stg = sb + (kt & 1) * FSTG;

        float sacc[8][4];
#pragma unroll
        for (int j = 0; j < 8; j++)
#pragma unroll
            for (int k = 0; k < 4; k++) sacc[j][k] = 0.f;
#pragma unroll
        for (int ks = 0; ks < 4; ks++) {
            uint32_t kh[4][4], kl[4][4];
#pragma unroll
            for (int p = 0; p < 4; p++) {
                uint32_t off = (p * 16 + lrow) * FTSTR + (ks * 2 + l16) * 16;
                ldsm4(kh[p], stg + off);
                ldsm4(kl[p], stg + KT_B + off);
            }
#pragma unroll
            for (int p = 0; p < 4; p++)
#pragma unroll
                for (int od = 0; od < 2; od++) {
                    float* s = sacc[p * 2 + od];
                    mma16816(s, qh[ks], kh[p][od], kh[p][od + 2]);
                    mma16816(s, qh[ks], kl[p][od], kl[p][od + 2]);
                    mma16816(s, ql[ks], kh[p][od], kh[p][od + 2]);
                }
        }

        if (kt >= 2 * qb) {
            int cb = kt * 64 + colb;
#pragma unroll
            for (int j = 0; j < 8; j++) {
                int c0 = cb + j * 8;
                if (c0 > r0g)     sacc[j][0] = -1e30f;
                if (c0 + 1 > r0g) sacc[j][1] = -1e30f;
                if (c0 > r0g + 8)     sacc[j][2] = -1e30f;
                if (c0 + 1 > r0g + 8) sacc[j][3] = -1e30f;
            }
        }

        float mx0 = -1e30f, mx1 = -1e30f;
#pragma unroll
        for (int j = 0; j < 8; j++) {
            mx0 = fmaxf(mx0, fmaxf(sacc[j][0], sacc[j][1]));
            mx1 = fmaxf(mx1, fmaxf(sacc[j][2], sacc[j][3]));
        }
        mx0 = fmaxf(mx0, __shfl_xor_sync(0xffffffffu, mx0, 1));
        mx0 = fmaxf(mx0, __shfl_xor_sync(0xffffffffu, mx0, 2));
        mx1 = fmaxf(mx1, __shfl_xor_sync(0xffffffffu, mx1, 1));
        mx1 = fmaxf(mx1, __shfl_xor_sync(0xffffffffu, mx1, 2));
        float mn0 = fmaxf(m0, mx0), mn1 = fmaxf(m1, mx1);
        float cr0 = __expf(m0 - mn0), cr1 = __expf(m1 - mn1);
        float ps0 = 0.f, ps1 = 0.f;
#pragma unroll
        for (int j = 0; j < 8; j++) {
            sacc[j][0] = __expf(sacc[j][0] - mn0); ps0 += sacc[j][0];
            sacc[j][1] = __expf(sacc[j][1] - mn0); ps0 += sacc[j][1];
            sacc[j][2] = __expf(sacc[j][2] - mn1); ps1 += sacc[j][2];
            sacc[j][3] = __expf(sacc[j][3] - mn1); ps1 += sacc[j][3];
        }
        ps0 += __shfl_xor_sync(0xffffffffu, ps0, 1);
        ps0 += __shfl_xor_sync(0xffffffffu, ps0, 2);
        ps1 += __shfl_xor_sync(0xffffffffu, ps1, 1);
        ps1 += __shfl_xor_sync(0xffffffffu, ps1, 2);
        l0 = l0 * cr0 + ps0; l1 = l1 * cr1 + ps1;
        m0 = mn0; m1 = mn1;
#pragma unroll
        for (int t = 0; t < 16; t++) {
            oacc[t][0] *= cr0; oacc[t][1] *= cr0;
            oacc[t][2] *= cr1; oacc[t][3] *= cr1;
        }

        uint32_t phf[4][4], plf[4][4];
#pragma unroll
        for (int j2 = 0; j2 < 4; j2++) {
            float* ta = sacc[2 * j2];
            float* tb = sacc[2 * j2 + 1];
            phf[j2][0] = packbf(ta[0], ta[1]);
            phf[j2][1] = packbf(ta[2], ta[3]);
            phf[j2][2] = packbf(tb[0], tb[1]);
            phf[j2][3] = packbf(tb[2], tb[3]);
            plf[j2][0] = packbf(ta[0] - bflo(phf[j2][0]), ta[1] - bfhi(phf[j2][0]));
            plf[j2][1] = packbf(ta[2] - bflo(phf[j2][1]), ta[3] - bfhi(phf[j2][1]));
            plf[j2][2] = packbf(tb[0] - bflo(phf[j2][2]), tb[1] - bfhi(phf[j2][2]));
            plf[j2][3] = packbf(tb[2] - bflo(phf[j2][3]), tb[3] - bfhi(phf[j2][3]));
        }

#pragma unroll
        for (int ks = 0; ks < 4; ks++) {
            uint32_t vf[8][4];
#pragma unroll
            for (int p = 0; p < 8; p++)
                ldsm4(vf[p], stg + 2 * KT_B + (p * 16 + lrow) * FTSTR + (ks * 2 + l16) * 16);
#pragma unroll
            for (int p = 0; p < 8; p++)
#pragma unroll
                for (int od = 0; od < 2; od++) {
                    mma16816(oacc[p * 2 + od], phf[ks], vf[p][od], vf[p][od + 2]);
                    mma16816(oacc[p * 2 + od], plf[ks], vf[p][od], vf[p][od + 2]);
                }
#pragma unroll
            for (int p = 0; p < 8; p++)
                ldsm4(vf[p], stg + 2 * KT_B + VT_B + (p * 16 + lrow) * FTSTR + (ks * 2 + l16) * 16);
#pragma unroll
            for (int p = 0; p < 8; p++)
#pragma unroll
                for (int od = 0; od < 2; od++)
                    mma16816(oacc[p * 2 + od], phf[ks], vf[p][od], vf[p][od + 2]);
        }
        __syncthreads();
    }

    float i0 = 1.f / l0, i1 = 1.f / l1;
    float* orow0 = Og + (size_t)(qb * 128 + wid * 16 + (lane >> 2)) * HDIM;
    float* orow1 = orow0 + 8 * HDIM;
#pragma unroll
    for (int t = 0; t < 16; t++) {
        int col = t * 8 + colb;
        *(float2*)(orow0 + col) = make_float2(oacc[t][0] * i0, oacc[t][1] * i0);
        *(float2*)(orow1 + col) = make_float2(oacc[t][2] * i1, oacc[t][3] * i1);
    }
}

// ---------------- combine: diff + RMSNorm + subln + 0.8 + bf16 split ---------
__global__ void combine_kernel(const float* __restrict__ subln) {
    int row = blockIdx.x * 8 + (threadIdx.x >> 5);
    int lane = threadIdx.x & 31;
    size_t off = (size_t)row * HDIM + lane * 4;
    float lam = g_lambda;
    float4 x1 = *(const float4*)(g_attn1 + off);
    float4 x2 = *(const float4*)(g_attn2 + off);
    float v0 = x1.x - lam * x2.x;
    float v1 = x1.y - lam * x2.y;
    float v2 = x1.z - lam * x2.z;
    float v3 = x1.w - lam * x2.w;
    float ss = v0 * v0 + v1 * v1 + v2 * v2 + v3 * v3;
#pragma unroll
    for (int o = 16; o; o >>= 1) ss += __shfl_xor_sync(0xffffffffu, ss, o);
    float rms = rsqrtf(ss * (1.0f / 128.0f) + 1e-5f);
    const float4 sw = *(const float4*)(subln + lane * 4);
    v0 *= rms * sw.x * 0.8f;
    v1 *= rms * sw.y * 0.8f;
    v2 *= rms * sw.z * 0.8f;
    v3 *= rms * sw.w * 0.8f;
    uint32_t h01 = packbf(v0, v1), h23 = packbf(v2, v3);
    uint32_t l01 = packbf(v0 - bflo(h01), v1 - bfhi(h01));
    uint32_t l23 = packbf(v2 - bflo(h23), v3 - bfhi(h23));
    *(uint2*)(g_ahi + off) = make_uint2(h01, h23);
    *(uint2*)(g_alo + off) = make_uint2(l01, l23);
}

// ---------------- launch -----------------------------------------------------
extern "C" void kernel_launch(void* const* d_in, const int* in_sizes, int n_in,
                              void* d_out, int out_size) {
    const float* x    = (const float*)d_in[0];
    const float* fc   = (const float*)d_in[1];
    const float* lq1  = (const float*)d_in[6];
    const float* lk1  = (const float*)d_in[7];
    const float* lq2  = (const float*)d_in[8];
    const float* lk2  = (const float*)d_in[9];
    const float* subw = (const float*)d_in[10];
    float* out = (float*)d_out;

    float *xq_p, *xk_p, *xv_p;
    __nv_bfloat16 *xhi, *xlo, *ahi, *alo, *whi, *wlo;
    cudaGetSymbolAddress((void**)&xq_p, g_xq);
    cudaGetSymbolAddress((void**)&xk_p, g_xk);
    cudaGetSymbolAddress((void**)&xv_p, g_xv);
    cudaGetSymbolAddress((void**)&xhi, g_xhi);
    cudaGetSymbolAddress((void**)&xlo, g_xlo);
    cudaGetSymbolAddress((void**)&ahi, g_ahi);
    cudaGetSymbolAddress((void**)&alo, g_alo);
    cudaGetSymbolAddress((void**)&whi, g_whi);
    cudaGetSymbolAddress((void**)&wlo, g_wlo);

    const int NX = BATCH * SEQ * DMODEL;          // 8388608
    const int NW = DMODEL * DMODEL;               // 4194304
    const int NP = BATCH * SEQ * NHEADS * HHDIM;  // 4194304

    split_bf16<<<NX / 1024, 256>>>(x, xhi, xlo, NX);
    {
        WSplit4 ws = {{(const float*)d_in[2], (const float*)d_in[3],
                       (const float*)d_in[4], (const float*)d_in[5]}};
        split_bf16_w4<<<dim3(NW / 1024, 4), 256>>>(ws, whi, wlo);
    }

    cudaFuncSetAttribute(gemm_mma, cudaFuncAttributeMaxDynamicSharedMemorySize, GEMM_SMEM);
    {
        GemmB bq = {whi + 0 * (size_t)NW, wlo + 0 * (size_t)NW, xq_p};
        GemmB bk = {whi + 1 * (size_t)NW, wlo + 1 * (size_t)NW, xk_p};
        GemmB bv = {whi + 2 * (size_t)NW, wlo + 2 * (size_t)NW, xv_p};
        gemm_mma<<<dim3(DMODEL / 128, (BATCH * SEQ) / 256, 3), 512, GEMM_SMEM>>>(
            xhi, xlo, bq, bk, bv);
    }

    rope_split_kernel<<<dim3(NP / 256, 2), 256>>>(fc);
    vsplitT_kernel<<<dim3(SEQ / 32, HDIM / 32, BATCH * NHEADS), 256>>>();
    lambda_kernel<<<1, 32>>>(lq1, lk1, lq2, lk2);

    cudaFuncSetAttribute(flash_hmma, cudaFuncAttributeMaxDynamicSharedMemorySize, FLASH_SMEM);
    flash_hmma<<<dim3(SEQ / 128, BATCH * NHEADS, 2), 256, FLASH_SMEM>>>();

    combine_kernel<<<(BATCH * NHEADS * SEQ) / 8, 256>>>(subw);

    {
        GemmB bo = {whi + 3 * (size_t)NW, wlo + 3 * (size_t)NW, out};
        gemm_mma<<<dim3(DMODEL / 128, (BATCH * SEQ) / 256, 1), 512, GEMM_SMEM>>>(
            ahi, alo, bo, bo, bo);
    }
}